// round 14
// baseline (speedup 1.0000x reference)
#include <cuda_runtime.h>
#include <cstdint>

// ---------------------------------------------------------------------------
// RelativeDifferenceLoss: mean over N of (y==0 ? |x-y| : |x-y|/y)
// Persistent warp-specialized bulk-async pipeline:
//   296 CTAs (2/SM) x 544 threads = 512 consumers + 1 producer warp.
//   6-stage x 16KB smem ring, per-stage full/empty mbarriers (no __syncthreads
//   in the hot loop). Last-block-done final reduce.
// ---------------------------------------------------------------------------

#define GRID          296
#define NTHREADS      544
#define NCONSUMERS    512
#define NCWARPS       (NCONSUMERS / 32)    // 16 consumer warps
#define NWARPS        (NTHREADS / 32)      // 17
#define STAGES        6
#define CHUNK_FLOATS  2048                 // per array per stage (8192 B)
#define CHUNK_BYTES   (CHUNK_FLOATS * 4)
#define STAGE_FLOATS  (2 * CHUNK_FLOATS)
#define STAGE_TX      (2 * CHUNK_BYTES)    // 16384
#define SMEM_BYTES    (STAGES * STAGE_TX)  // 98304

__device__ float        g_partials[GRID];
__device__ unsigned int g_count = 0;

// ---- PTX helpers ----
__device__ __forceinline__ uint32_t smem_u32(const void* p) {
    uint32_t a;
    asm("{ .reg .u64 t; cvta.to.shared.u64 t, %1; cvt.u32.u64 %0, t; }"
        : "=r"(a) : "l"(p));
    return a;
}
__device__ __forceinline__ void mbar_init(uint32_t bar, uint32_t cnt) {
    asm volatile("mbarrier.init.shared.b64 [%0], %1;" :: "r"(bar), "r"(cnt) : "memory");
}
__device__ __forceinline__ void mbar_arrive(uint32_t bar) {
    asm volatile("mbarrier.arrive.shared.b64 _, [%0];" :: "r"(bar) : "memory");
}
__device__ __forceinline__ void mbar_expect_tx(uint32_t bar, uint32_t bytes) {
    asm volatile("mbarrier.arrive.expect_tx.shared.b64 _, [%0], %1;"
                 :: "r"(bar), "r"(bytes) : "memory");
}
__device__ __forceinline__ void mbar_wait_parity(uint32_t bar, uint32_t phase) {
    asm volatile(
        "{\n\t"
        ".reg .pred P;\n\t"
        "WL%=:\n\t"
        "mbarrier.try_wait.parity.acquire.cta.shared::cta.b64 P, [%0], %1, 0x989680;\n\t"
        "@P bra WD%=;\n\t"
        "bra WL%=;\n\t"
        "WD%=:\n\t"
        "}"
        :: "r"(bar), "r"(phase) : "memory");
}
__device__ __forceinline__ void fence_proxy_async_cta() {
    asm volatile("fence.proxy.async.shared::cta;" ::: "memory");
}
__device__ __forceinline__ void bulk_g2s(uint32_t dst, const void* src,
                                         uint32_t bytes, uint32_t bar) {
    asm volatile(
        "cp.async.bulk.shared::cluster.global.mbarrier::complete_tx::bytes "
        "[%0], [%1], %2, [%3];"
        :: "r"(dst), "l"(src), "r"(bytes), "r"(bar) : "memory");
}

__device__ __forceinline__ float rel_term(float x, float y) {
    float ad = fabsf(x - y);
    return (y == 0.0f) ? ad : __fdividef(ad, y);   // signed y, matching reference
}
__device__ __forceinline__ float quad(float4 xv, float4 yv) {
    return rel_term(xv.x, yv.x) + rel_term(xv.y, yv.y)
         + rel_term(xv.z, yv.z) + rel_term(xv.w, yv.w);
}

extern __shared__ float sm_ring[];   // [STAGES][2*CHUNK_FLOATS]: x then y

__global__ void __launch_bounds__(NTHREADS)
rdl_ws_kernel(const float* __restrict__ x,
              const float* __restrict__ y,
              int n, float inv_n, float* __restrict__ out)
{
    __shared__ alignas(8) unsigned long long s_full[STAGES];
    __shared__ alignas(8) unsigned long long s_empty[STAGES];
    __shared__ float s_warp[NWARPS];
    __shared__ bool  s_is_last;

    const int tid = threadIdx.x;
    float acc = 0.0f;

    const int nchunks = n / CHUNK_FLOATS;
    const bool fast = (n % CHUNK_FLOATS == 0);

    const uint32_t full0  = smem_u32(&s_full[0]);
    const uint32_t empty0 = smem_u32(&s_empty[0]);

    if (fast) {
        const int iters = (nchunks - (int)blockIdx.x + GRID - 1) / GRID;

        if (tid == 0) {
            #pragma unroll
            for (int s = 0; s < STAGES; s++) {
                mbar_init(full0  + 8u * s, 1);         // TMA expect_tx arrive
                mbar_init(empty0 + 8u * s, NCWARPS);   // one arrive per consumer warp
            }
            fence_proxy_async_cta();
        }
        __syncthreads();

        if (tid == NCONSUMERS) {
            // ---------------- producer (single thread) ----------------
            int st = 0, eph = 1;   // phase=1: first STAGES empty-waits pass
            for (int j = 0; j < iters; j++) {
                mbar_wait_parity(empty0 + 8u * st, (uint32_t)eph);
                uint32_t fb = full0 + 8u * st;
                long long c = (long long)blockIdx.x + (long long)j * GRID;
                mbar_expect_tx(fb, STAGE_TX);
                bulk_g2s(smem_u32(&sm_ring[st * STAGE_FLOATS]),
                         x + c * CHUNK_FLOATS, CHUNK_BYTES, fb);
                bulk_g2s(smem_u32(&sm_ring[st * STAGE_FLOATS + CHUNK_FLOATS]),
                         y + c * CHUNK_FLOATS, CHUNK_BYTES, fb);
                if (++st == STAGES) { st = 0; eph ^= 1; }
            }
        } else if (tid < NCONSUMERS) {
            // ---------------- consumers (16 warps) ----------------
            const int lane = tid & 31;
            int st = 0, ph = 0;
            for (int j = 0; j < iters; j++) {
                mbar_wait_parity(full0 + 8u * st, (uint32_t)ph);

                const float4* sxv = (const float4*)&sm_ring[st * STAGE_FLOATS];
                const float4* syv = (const float4*)&sm_ring[st * STAGE_FLOATS + CHUNK_FLOATS];
                float4 xa = sxv[tid];
                float4 ya = syv[tid];

                __syncwarp();                          // warp's reads done
                if (lane == 0) mbar_arrive(empty0 + 8u * st);  // free stage ASAP

                acc += quad(xa, ya);

                if (++st == STAGES) { st = 0; ph ^= 1; }
            }
        }
    } else {
        // generic fallback: plain grid-stride LDG
        int n4 = n >> 2;
        const float4* x4 = (const float4*)x;
        const float4* y4 = (const float4*)y;
        for (int i = blockIdx.x * NTHREADS + tid; i < n4; i += GRID * NTHREADS)
            acc += quad(x4[i], y4[i]);
        for (int i = (n4 << 2) + blockIdx.x * NTHREADS + tid; i < n; i += GRID * NTHREADS)
            acc += rel_term(x[i], y[i]);
    }

    // ---- block reduce (producer contributes 0) ----
    #pragma unroll
    for (int off = 16; off > 0; off >>= 1)
        acc += __shfl_down_sync(0xFFFFFFFFu, acc, off);

    int lane = tid & 31;
    int wid  = tid >> 5;
    if (lane == 0) s_warp[wid] = acc;
    __syncthreads();

    if (tid == 0) {
        float v = 0.0f;
        #pragma unroll
        for (int w = 0; w < NWARPS; w++) v += s_warp[w];
        g_partials[blockIdx.x] = v;
        __threadfence();
        unsigned int prev = atomicAdd(&g_count, 1u);
        s_is_last = (prev == (unsigned)(gridDim.x - 1));
    }
    __syncthreads();

    // ---- last block: deterministic final reduce ----
    if (s_is_last) {
        float v = 0.0f;
        for (int i = tid; i < GRID; i += NTHREADS)
            v += g_partials[i];

        #pragma unroll
        for (int off = 16; off > 0; off >>= 1)
            v += __shfl_down_sync(0xFFFFFFFFu, v, off);

        if (lane == 0) s_warp[wid] = v;
        __syncthreads();

        if (tid == 0) {
            float t = 0.0f;
            #pragma unroll
            for (int w = 0; w < NWARPS; w++) t += s_warp[w];
            out[0]  = t * inv_n;
            g_count = 0;   // reset for next graph replay
        }
    }
}

extern "C" void kernel_launch(void* const* d_in, const int* in_sizes, int n_in,
                              void* d_out, int out_size)
{
    const float* x = (const float*)d_in[0];
    const float* y = (const float*)d_in[1];
    float* out = (float*)d_out;

    int n = in_sizes[0];   // 33554432

    cudaFuncSetAttribute(rdl_ws_kernel,
                         cudaFuncAttributeMaxDynamicSharedMemorySize, SMEM_BYTES);

    rdl_ws_kernel<<<GRID, NTHREADS, SMEM_BYTES>>>(x, y, n, 1.0f / (float)n, out);
}

// round 15
// speedup vs baseline: 1.0265x; 1.0265x over previous
#include <cuda_runtime.h>
#include <cstdint>

// ---------------------------------------------------------------------------
// RelativeDifferenceLoss: mean over N of (y==0 ? |x-y| : |x-y|/y)
// Persistent bulk-async pipeline (R12 structure): 296 CTAs (2/SM) x 512 thr,
// 3-stage x 32KB smem ring (16KB x + 16KB y per stage), cp.async.bulk with
// L2 evict_first hint, last-block-done final reduce.
// ---------------------------------------------------------------------------

#define GRID          296                  // 2 CTAs x 148 SMs, persistent
#define NTHREADS      512
#define STAGES        3
#define CHUNK_FLOATS  4096                 // per array per stage (16384 B)
#define CHUNK_BYTES   (CHUNK_FLOATS * 4)   // 16384
#define STAGE_FLOATS  (2 * CHUNK_FLOATS)   // x + y per stage
#define STAGE_TX      (2 * CHUNK_BYTES)    // 32768
#define SMEM_BYTES    (STAGES * STAGE_TX)  // 98304 (96 KB)

__device__ float        g_partials[GRID];
__device__ unsigned int g_count = 0;

// ---- PTX helpers ----
__device__ __forceinline__ uint32_t smem_u32(const void* p) {
    uint32_t a;
    asm("{ .reg .u64 t; cvta.to.shared.u64 t, %1; cvt.u32.u64 %0, t; }"
        : "=r"(a) : "l"(p));
    return a;
}
__device__ __forceinline__ void mbar_init(uint32_t bar, uint32_t cnt) {
    asm volatile("mbarrier.init.shared.b64 [%0], %1;" :: "r"(bar), "r"(cnt) : "memory");
}
__device__ __forceinline__ void mbar_expect_tx(uint32_t bar, uint32_t bytes) {
    asm volatile("mbarrier.arrive.expect_tx.shared.b64 _, [%0], %1;"
                 :: "r"(bar), "r"(bytes) : "memory");
}
__device__ __forceinline__ void mbar_wait_parity(uint32_t bar, uint32_t phase) {
    asm volatile(
        "{\n\t"
        ".reg .pred P;\n\t"
        "WL%=:\n\t"
        "mbarrier.try_wait.parity.acquire.cta.shared::cta.b64 P, [%0], %1, 0x989680;\n\t"
        "@P bra WD%=;\n\t"
        "bra WL%=;\n\t"
        "WD%=:\n\t"
        "}"
        :: "r"(bar), "r"(phase) : "memory");
}
__device__ __forceinline__ void fence_proxy_async_cta() {
    asm volatile("fence.proxy.async.shared::cta;" ::: "memory");
}
// bulk G2S with L2 evict_first hint (stream-once data; don't thrash L2)
__device__ __forceinline__ void bulk_g2s(uint32_t dst, const void* src,
                                         uint32_t bytes, uint32_t bar) {
    asm volatile(
        "{\n\t"
        ".reg .b64 pol;\n\t"
        "createpolicy.fractional.L2::evict_first.b64 pol, 1.0;\n\t"
        "cp.async.bulk.shared::cluster.global.mbarrier::complete_tx::bytes.L2::cache_hint "
        "[%0], [%1], %2, [%3], pol;\n\t"
        "}"
        :: "r"(dst), "l"(src), "r"(bytes), "r"(bar) : "memory");
}

__device__ __forceinline__ float rel_term(float x, float y) {
    float ad = fabsf(x - y);
    return (y == 0.0f) ? ad : __fdividef(ad, y);   // signed y, matching reference
}
__device__ __forceinline__ float quad(float4 xv, float4 yv) {
    return rel_term(xv.x, yv.x) + rel_term(xv.y, yv.y)
         + rel_term(xv.z, yv.z) + rel_term(xv.w, yv.w);
}

extern __shared__ float sm_ring[];   // [STAGES][2*CHUNK_FLOATS]: x then y

__global__ void __launch_bounds__(NTHREADS)
rdl_bulk_kernel(const float* __restrict__ x,
                const float* __restrict__ y,
                int n, float inv_n, float* __restrict__ out)
{
    __shared__ alignas(8) unsigned long long s_bar[STAGES];
    __shared__ float s_warp[NTHREADS / 32];
    __shared__ bool  s_is_last;

    const int tid = threadIdx.x;
    float acc0 = 0.0f, acc1 = 0.0f;

    const int nchunks = n / CHUNK_FLOATS;
    const bool fast = (n % CHUNK_FLOATS == 0);

    if (fast) {
        const int iters = (nchunks - (int)blockIdx.x + GRID - 1) / GRID;
        const uint32_t bar0 = smem_u32(&s_bar[0]);

        if (tid == 0) {
            #pragma unroll
            for (int s = 0; s < STAGES; s++) mbar_init(bar0 + 8u * s, 1);
            fence_proxy_async_cta();
            int pre = iters < STAGES ? iters : STAGES;
            for (int s = 0; s < pre; s++) {
                uint32_t bar = bar0 + 8u * s;
                long long c = (long long)blockIdx.x + (long long)s * GRID;
                mbar_expect_tx(bar, STAGE_TX);
                bulk_g2s(smem_u32(&sm_ring[s * STAGE_FLOATS]),
                         x + c * CHUNK_FLOATS, CHUNK_BYTES, bar);
                bulk_g2s(smem_u32(&sm_ring[s * STAGE_FLOATS + CHUNK_FLOATS]),
                         y + c * CHUNK_FLOATS, CHUNK_BYTES, bar);
            }
        }
        __syncthreads();

        int st = 0, ph = 0;
        for (int j = 0; j < iters; j++) {
            mbar_wait_parity(bar0 + 8u * st, (uint32_t)ph);

            // stage -> registers: 2 float4 per array per thread (512 thr)
            const float4* sxv = (const float4*)&sm_ring[st * STAGE_FLOATS];
            const float4* syv = (const float4*)&sm_ring[st * STAGE_FLOATS + CHUNK_FLOATS];
            float4 xa = sxv[tid];
            float4 xb = sxv[tid + NTHREADS];
            float4 ya = syv[tid];
            float4 yb = syv[tid + NTHREADS];

            __syncthreads();                 // stage fully consumed

            // early refill: request in flight before the math
            if (tid == 0 && j + STAGES < iters) {
                uint32_t bar = bar0 + 8u * st;
                long long c = (long long)blockIdx.x + (long long)(j + STAGES) * GRID;
                mbar_expect_tx(bar, STAGE_TX);
                bulk_g2s(smem_u32(&sm_ring[st * STAGE_FLOATS]),
                         x + c * CHUNK_FLOATS, CHUNK_BYTES, bar);
                bulk_g2s(smem_u32(&sm_ring[st * STAGE_FLOATS + CHUNK_FLOATS]),
                         y + c * CHUNK_FLOATS, CHUNK_BYTES, bar);
            }

            acc0 += quad(xa, ya);
            acc1 += quad(xb, yb);

            if (++st == STAGES) { st = 0; ph ^= 1; }
        }
    } else {
        // generic fallback: plain grid-stride LDG
        int n4 = n >> 2;
        const float4* x4 = (const float4*)x;
        const float4* y4 = (const float4*)y;
        for (int i = blockIdx.x * NTHREADS + tid; i < n4; i += GRID * NTHREADS)
            acc0 += quad(x4[i], y4[i]);
        for (int i = (n4 << 2) + blockIdx.x * NTHREADS + tid; i < n; i += GRID * NTHREADS)
            acc0 += rel_term(x[i], y[i]);
    }

    float acc = acc0 + acc1;

    // ---- block reduce ----
    #pragma unroll
    for (int off = 16; off > 0; off >>= 1)
        acc += __shfl_down_sync(0xFFFFFFFFu, acc, off);

    int lane = tid & 31;
    int wid  = tid >> 5;
    if (lane == 0) s_warp[wid] = acc;
    __syncthreads();

    if (tid == 0) {
        float v = 0.0f;
        #pragma unroll
        for (int w = 0; w < NTHREADS / 32; w++) v += s_warp[w];
        g_partials[blockIdx.x] = v;
        __threadfence();
        unsigned int prev = atomicAdd(&g_count, 1u);
        s_is_last = (prev == (unsigned)(gridDim.x - 1));
    }
    __syncthreads();

    // ---- last block: deterministic final reduce ----
    if (s_is_last) {
        float v = 0.0f;
        for (int i = tid; i < GRID; i += NTHREADS)
            v += g_partials[i];

        #pragma unroll
        for (int off = 16; off > 0; off >>= 1)
            v += __shfl_down_sync(0xFFFFFFFFu, v, off);

        if (lane == 0) s_warp[wid] = v;
        __syncthreads();

        if (tid == 0) {
            float t = 0.0f;
            #pragma unroll
            for (int w = 0; w < NTHREADS / 32; w++) t += s_warp[w];
            out[0]  = t * inv_n;
            g_count = 0;   // reset for next graph replay
        }
    }
}

extern "C" void kernel_launch(void* const* d_in, const int* in_sizes, int n_in,
                              void* d_out, int out_size)
{
    const float* x = (const float*)d_in[0];
    const float* y = (const float*)d_in[1];
    float* out = (float*)d_out;

    int n = in_sizes[0];   // 33554432

    cudaFuncSetAttribute(rdl_bulk_kernel,
                         cudaFuncAttributeMaxDynamicSharedMemorySize, SMEM_BYTES);

    rdl_bulk_kernel<<<GRID, NTHREADS, SMEM_BYTES>>>(x, y, n, 1.0f / (float)n, out);
}